// round 8
// baseline (speedup 1.0000x reference)
#include <cuda_runtime.h>
#include <math_constants.h>

#define BB 8
#define HH 3
#define PP 4096
#define NPTS (BB * PP)
#define NCELL 512
#define TSZ 64
#define NTILE (PP / TSZ)        // 64 tiles/batch
#define TPAIR (TSZ / 2)         // 32 pairs/tile
#define WPB 4                   // warps (p-tiles) per block
#define TP (WPB * 32)
#define NSQ 8                   // q splits
#define TPS (NTILE / NSQ)       // 8 tiles per split
#define NBLK 128
#define MARGIN 2e-3f

__device__ float g_px[NPTS], g_py[NPTS], g_pz[NPTS], g_pw[NPTS];
__device__ float g_pd0[NPTS], g_pd1[NPTS], g_pd2[NPTS];
__device__ ulonglong2         g_A[NPTS / 2];
__device__ ulonglong2         g_Bq[NPTS / 2];
__device__ ulonglong2         g_C[NPTS / 2];
__device__ unsigned long long g_D[NPTS / 2];
__device__ float g_meta[BB][NTILE][HH][8];
__device__ int   g_cellstart[BB][NCELL + 1];
__device__ unsigned int g_minbits[HH * NPTS];
__device__ float g_partial[NBLK];

__device__ __forceinline__ unsigned long long pack2(float lo, float hi) {
    unsigned long long d;
    asm("mov.b64 %0, {%1, %2};" : "=l"(d) : "f"(lo), "f"(hi));
    return d;
}
__device__ __forceinline__ unsigned long long fma2(unsigned long long a,
                                                   unsigned long long b,
                                                   unsigned long long c) {
    unsigned long long d;
    asm("fma.rn.f32x2 %0, %1, %2, %3;" : "=l"(d) : "l"(a), "l"(b), "l"(c));
    return d;
}
__device__ __forceinline__ void min2(float& a, float& b, unsigned long long t) {
    float lo, hi;
    asm("mov.b64 {%0, %1}, %2;" : "=f"(lo), "=f"(hi) : "l"(t));
    a = fminf(a, lo);
    b = fminf(b, hi);
}

__device__ __forceinline__ void load_normals(const float* __restrict__ planes,
                                             int b, float nx[HH], float ny[HH],
                                             float nz[HH], float nc[HH]) {
#pragma unroll
    for (int h = 0; h < HH; h++) {
        const float* pl = planes + (b * HH + h) * 4;
        float x = pl[0], y = pl[1], z = pl[2];
        float nn = x * x + y * y + z * z;
        float inv = rsqrtf(nn);
        inv = inv * (1.5f - 0.5f * nn * inv * inv);
        nx[h] = x * inv; ny[h] = y * inv; nz[h] = z * inv; nc[h] = pl[3];
    }
}
__device__ __forceinline__ int cell_coord(float v) {
    int c = (int)((v + 5.25f) * 0.7619048f);
    return min(7, max(0, c));
}
__device__ __forceinline__ int morton_cell(float x, float y, float z) {
    int cx = cell_coord(x), cy = cell_coord(y), cz = cell_coord(z);
    int code = 0;
#pragma unroll
    for (int k = 0; k < 3; k++) {
        code |= ((cx >> k) & 1) << (3 * k + 2);
        code |= ((cy >> k) & 1) << (3 * k + 1);
        code |= ((cz >> k) & 1) << (3 * k + 0);
    }
    return code;
}
__device__ __forceinline__ float wred_min(float v) {
#pragma unroll
    for (int o = 16; o; o >>= 1) v = fminf(v, __shfl_xor_sync(~0u, v, o));
    return v;
}
__device__ __forceinline__ float wred_max(float v) {
#pragma unroll
    for (int o = 16; o; o >>= 1) v = fmaxf(v, __shfl_xor_sync(~0u, v, o));
    return v;
}

// ---- sort: one block per batch; counting sort by Morton cell + tile bboxes
__global__ __launch_bounds__(512)
void sort_kernel(const float* __restrict__ planes,
                 const float* __restrict__ pts) {
    __shared__ int sh_hist[NCELL], sh_a[NCELL], sh_b[NCELL];
    __shared__ int sh_start[NCELL], sh_cnt[NCELL];
    const int b = blockIdx.x, t = threadIdx.x;

    float nx[HH], ny[HH], nz[HH], nc[HH];
    load_normals(planes, b, nx, ny, nz, nc);

    sh_hist[t] = 0;
    __syncthreads();

    float X[8], Y[8], Z[8];
    int C8[8];
#pragma unroll
    for (int k = 0; k < 8; k++) {
        int i = k * 512 + t;
        const float* p = pts + (b * PP + i) * 3;
        X[k] = p[0]; Y[k] = p[1]; Z[k] = p[2];
        C8[k] = morton_cell(X[k], Y[k], Z[k]);
        atomicAdd(&sh_hist[C8[k]], 1);
    }
    __syncthreads();

    sh_a[t] = sh_hist[t];
    __syncthreads();
    int* src = sh_a; int* dst = sh_b;
    for (int off = 1; off < NCELL; off <<= 1) {
        int v = src[t];
        if (t >= off) v += src[t - off];
        dst[t] = v;
        __syncthreads();
        int* tmp = src; src = dst; dst = tmp;
    }
    int start = src[t] - sh_hist[t];
    sh_start[t] = start; sh_cnt[t] = 0;
    g_cellstart[b][t] = start;
    if (t == 0) g_cellstart[b][NCELL] = PP;
    __syncthreads();

#pragma unroll
    for (int k = 0; k < 8; k++) {
        int pos = sh_start[C8[k]] + atomicAdd(&sh_cnt[C8[k]], 1);
        float x = X[k], y = Y[k], z = Z[k];
        float w = x * x + y * y + z * z;
        float d0 = nx[0] * x + ny[0] * y + nz[0] * z + nc[0];
        float d1 = nx[1] * x + ny[1] * y + nz[1] * z + nc[1];
        float d2 = nx[2] * x + ny[2] * y + nz[2] * z + nc[2];
        int gi = b * PP + pos;
        g_px[gi] = x; g_py[gi] = y; g_pz[gi] = z; g_pw[gi] = w;
        g_pd0[gi] = d0; g_pd1[gi] = d1; g_pd2[gi] = d2;
        int pr = gi >> 1, ln = gi & 1;
        unsigned int* Au = (unsigned int*)&g_A[pr];
        unsigned int* Bu = (unsigned int*)&g_Bq[pr];
        unsigned int* Cu = (unsigned int*)&g_C[pr];
        unsigned int* Du = (unsigned int*)&g_D[pr];
        Au[0 + ln] = __float_as_uint(x);  Au[2 + ln] = __float_as_uint(y);
        Bu[0 + ln] = __float_as_uint(z);  Bu[2 + ln] = __float_as_uint(w);
        Cu[0 + ln] = __float_as_uint(d0); Cu[2 + ln] = __float_as_uint(d1);
        Du[0 + ln] = __float_as_uint(d2);
    }
    __syncthreads();

    // per-tile reflected bboxes (16 warps x 4 tiles)
    const int wid = t >> 5, lane = t & 31;
    for (int tile = wid; tile < NTILE; tile += 16) {
        float mnv[HH][3], mxv[HH][3];
#pragma unroll
        for (int h = 0; h < HH; h++)
#pragma unroll
            for (int d = 0; d < 3; d++) { mnv[h][d] = CUDART_INF_F; mxv[h][d] = -CUDART_INF_F; }
#pragma unroll
        for (int r = 0; r < 2; r++) {
            int gi = b * PP + tile * TSZ + r * 32 + lane;
            float x = g_px[gi], y = g_py[gi], z = g_pz[gi];
            float dh[HH] = {g_pd0[gi], g_pd1[gi], g_pd2[gi]};
#pragma unroll
            for (int h = 0; h < HH; h++) {
                float rx = x - 2.0f * dh[h] * nx[h];
                float ry = y - 2.0f * dh[h] * ny[h];
                float rz = z - 2.0f * dh[h] * nz[h];
                mnv[h][0] = fminf(mnv[h][0], rx); mxv[h][0] = fmaxf(mxv[h][0], rx);
                mnv[h][1] = fminf(mnv[h][1], ry); mxv[h][1] = fmaxf(mxv[h][1], ry);
                mnv[h][2] = fminf(mnv[h][2], rz); mxv[h][2] = fmaxf(mxv[h][2], rz);
            }
        }
#pragma unroll
        for (int h = 0; h < HH; h++) {
#pragma unroll
            for (int d = 0; d < 3; d++) {
                mnv[h][d] = wred_min(mnv[h][d]);
                mxv[h][d] = wred_max(mxv[h][d]);
            }
            if (lane == 0) {
                float* M = &g_meta[b][tile][h][0];
                M[0] = mnv[h][0]; M[1] = mnv[h][1]; M[2] = mnv[h][2]; M[3] = 0.f;
                M[4] = mxv[h][0]; M[5] = mxv[h][1]; M[6] = mxv[h][2]; M[7] = 0.f;
            }
        }
    }
}

// ---- seed: per point/head scan a 64-wide sorted window near reflected cell
__global__ __launch_bounds__(128)
void seed_kernel(const float* __restrict__ planes) {
    const int gi = blockIdx.x * 128 + threadIdx.x;
    const int b  = gi / PP;

    float nx[HH], ny[HH], nz[HH], nc[HH];
    load_normals(planes, b, nx, ny, nz, nc);

    const float px = g_px[gi], py = g_py[gi], pz = g_pz[gi];
    const float x2p = px * px + py * py + pz * pz;
    const float e0 = g_pd0[gi], e1 = g_pd1[gi], e2 = g_pd2[gi];
    const float eh[HH] = {e0, e1, e2};
    const float mx = -2.f * px, my = -2.f * py, mz = -2.f * pz;

#pragma unroll
    for (int h = 0; h < HH; h++) {
        float rx = px - 2.f * eh[h] * nx[h];
        float ry = py - 2.f * eh[h] * ny[h];
        float rz = pz - 2.f * eh[h] * nz[h];
        int cell = morton_cell(rx, ry, rz);
        int c0 = g_cellstart[b][cell], c1 = g_cellstart[b][cell + 1];
        int s = min(max(((c0 + c1) >> 1) - 32, 0), PP - 64);
        const float q4 = 4.f * eh[h];
        float m = CUDART_INF_F;
        const int base = b * PP + s;
        for (int j = 0; j < 64; j++) {
            int qi = base + j;
            float acc = fmaf(mx, g_px[qi], g_pw[qi]);
            acc = fmaf(my, g_py[qi], acc);
            acc = fmaf(mz, g_pz[qi], acc);
            float dq = (h == 0) ? g_pd0[qi] : (h == 1) ? g_pd1[qi] : g_pd2[qi];
            m = fminf(m, fmaf(q4, dq, acc));
        }
        float v = fmaxf(m + x2p, 0.f);
        atomicMin(&g_minbits[h * NPTS + gi], __float_as_uint(v));
    }
}

// ---- pruned chamfer: warp = 64 consecutive sorted p; skip far q-tiles
__global__ __launch_bounds__(TP)
void chamfer_kernel() {
    const int lane = threadIdx.x & 31;
    const int wid  = threadIdx.x >> 5;
    const int spl  = blockIdx.y;
    const int b    = blockIdx.z;
    const int ptile = blockIdx.x * WPB + wid;
    const int pbase0 = b * PP + ptile * TSZ;

    unsigned long long MX[2], MY[2], MZ[2], Q0[2], Q1[2], Q2[2];
    float x2p[2], mf0[2], mf1[2], mf2[2];
    float m0a[2], m0b[2], m1a[2], m1b[2], m2a[2], m2b[2];
    float plox = CUDART_INF_F, ploy = CUDART_INF_F, ploz = CUDART_INF_F;
    float phix = -CUDART_INF_F, phiy = -CUDART_INF_F, phiz = -CUDART_INF_F;

#pragma unroll
    for (int k = 0; k < 2; k++) {
        const int i = pbase0 + k * 32 + lane;
        float ax = g_px[i], ay = g_py[i], az = g_pz[i];
        MX[k] = pack2(-2.f * ax, -2.f * ax);
        MY[k] = pack2(-2.f * ay, -2.f * ay);
        MZ[k] = pack2(-2.f * az, -2.f * az);
        float e0 = g_pd0[i], e1 = g_pd1[i], e2 = g_pd2[i];
        Q0[k] = pack2(4.f * e0, 4.f * e0);
        Q1[k] = pack2(4.f * e1, 4.f * e1);
        Q2[k] = pack2(4.f * e2, 4.f * e2);
        x2p[k] = ax * ax + ay * ay + az * az;
        m0a[k] = m0b[k] = CUDART_INF_F;
        m1a[k] = m1b[k] = CUDART_INF_F;
        m2a[k] = m2b[k] = CUDART_INF_F;
        mf0[k] = __uint_as_float(g_minbits[0 * NPTS + i]);
        mf1[k] = __uint_as_float(g_minbits[1 * NPTS + i]);
        mf2[k] = __uint_as_float(g_minbits[2 * NPTS + i]);
        plox = fminf(plox, ax); phix = fmaxf(phix, ax);
        ploy = fminf(ploy, ay); phiy = fmaxf(phiy, ay);
        ploz = fminf(ploz, az); phiz = fmaxf(phiz, az);
    }
    plox = wred_min(plox); phix = wred_max(phix);
    ploy = wred_min(ploy); phiy = wred_max(phiy);
    ploz = wred_min(ploz); phiz = wred_max(phiz);

    float thr0 = wred_max(fmaxf(mf0[0], mf0[1])) + MARGIN;
    float thr1 = wred_max(fmaxf(mf1[0], mf1[1])) + MARGIN;
    float thr2 = wred_max(fmaxf(mf2[0], mf2[1])) + MARGIN;

    for (int it = 0; it < TPS; it++) {
        const int tq = spl * TPS + it;
        const float* M = &g_meta[b][tq][0][0];
        float lb[HH];
#pragma unroll
        for (int h = 0; h < HH; h++) {
            float4 mn = __ldg((const float4*)(M + h * 8));
            float4 mx = __ldg((const float4*)(M + h * 8 + 4));
            float dx = fmaxf(0.f, fmaxf(mn.x - phix, plox - mx.x));
            float dy = fmaxf(0.f, fmaxf(mn.y - phiy, ploy - mx.y));
            float dz = fmaxf(0.f, fmaxf(mn.z - phiz, ploz - mx.z));
            lb[h] = dx * dx + dy * dy + dz * dz;
        }
        if (lb[0] >= thr0 && lb[1] >= thr1 && lb[2] >= thr2) continue;

        const int qp = (b * PP) / 2 + tq * TPAIR;
#pragma unroll 4
        for (int j = 0; j < TPAIR; j++) {
            ulonglong2 A = __ldg(&g_A[qp + j]);
            ulonglong2 B = __ldg(&g_Bq[qp + j]);
            ulonglong2 C = __ldg(&g_C[qp + j]);
            unsigned long long D2 = __ldg(&g_D[qp + j]);
#pragma unroll
            for (int k = 0; k < 2; k++) {
                unsigned long long acc = fma2(MX[k], A.x, B.y);
                acc = fma2(MY[k], A.y, acc);
                acc = fma2(MZ[k], B.x, acc);
                min2(m0a[k], m0b[k], fma2(Q0[k], C.x, acc));
                min2(m1a[k], m1b[k], fma2(Q1[k], C.y, acc));
                min2(m2a[k], m2b[k], fma2(Q2[k], D2,  acc));
            }
        }
        float t0 = -CUDART_INF_F, t1 = -CUDART_INF_F, t2 = -CUDART_INF_F;
#pragma unroll
        for (int k = 0; k < 2; k++) {
            mf0[k] = fminf(mf0[k], fminf(m0a[k], m0b[k]) + x2p[k]);
            mf1[k] = fminf(mf1[k], fminf(m1a[k], m1b[k]) + x2p[k]);
            mf2[k] = fminf(mf2[k], fminf(m2a[k], m2b[k]) + x2p[k]);
            t0 = fmaxf(t0, mf0[k]); t1 = fmaxf(t1, mf1[k]); t2 = fmaxf(t2, mf2[k]);
        }
        thr0 = wred_max(t0) + MARGIN;
        thr1 = wred_max(t1) + MARGIN;
        thr2 = wred_max(t2) + MARGIN;
    }

#pragma unroll
    for (int k = 0; k < 2; k++) {
        const int i = pbase0 + k * 32 + lane;
        float v0 = fmaxf(fminf(m0a[k], m0b[k]) + x2p[k], 0.f);
        float v1 = fmaxf(fminf(m1a[k], m1b[k]) + x2p[k], 0.f);
        float v2 = fmaxf(fminf(m2a[k], m2b[k]) + x2p[k], 0.f);
        atomicMin(&g_minbits[0 * NPTS + i], __float_as_uint(v0));
        atomicMin(&g_minbits[1 * NPTS + i], __float_as_uint(v1));
        atomicMin(&g_minbits[2 * NPTS + i], __float_as_uint(v2));
    }
}

__global__ __launch_bounds__(256)
void combine_kernel() {
    __shared__ float red[256];
    const int i = blockIdx.x * 256 + threadIdx.x;
    float s = __uint_as_float(g_minbits[0 * NPTS + i])
            + __uint_as_float(g_minbits[1 * NPTS + i])
            + __uint_as_float(g_minbits[2 * NPTS + i]);
    red[threadIdx.x] = s;
    __syncthreads();
#pragma unroll
    for (int off = 128; off > 0; off >>= 1) {
        if (threadIdx.x < off) red[threadIdx.x] += red[threadIdx.x + off];
        __syncthreads();
    }
    if (threadIdx.x == 0) g_partial[blockIdx.x] = red[0];
}

__global__ __launch_bounds__(128)
void finalize_kernel(const float* __restrict__ planes, float* __restrict__ out) {
    __shared__ float red[128];
    __shared__ float regs[BB];
    const int t = threadIdx.x;
    red[t] = g_partial[t];
    __syncthreads();
#pragma unroll
    for (int off = 64; off > 0; off >>= 1) {
        if (t < off) red[t] += red[t + off];
        __syncthreads();
    }
    if (t < BB) {
        float nx[HH], ny[HH], nz[HH], nc[HH];
        load_normals(planes, t, nx, ny, nz, nc);
        float acc = 0.f;
#pragma unroll
        for (int i = 0; i < HH; i++)
#pragma unroll
            for (int j = 0; j < HH; j++) {
                float g = nx[i] * nx[j] + ny[i] * ny[j] + nz[i] * nz[j]
                        - (i == j ? 1.f : 0.f);
                acc += g * g;
            }
        regs[t] = sqrtf(acc);
    }
    __syncthreads();
    if (t == 0) {
        float reg = 0.f;
#pragma unroll
        for (int b = 0; b < BB; b++) reg += regs[b];
        float refl = 2.f * red[0] / (float)(BB * PP);
        out[0] = refl + 25.f * reg;
    }
}

extern "C" void kernel_launch(void* const* d_in, const int* in_sizes, int n_in,
                              void* d_out, int out_size) {
    const float* planes = (const float*)d_in[0];
    const float* pts    = (const float*)d_in[1];

    void* mb = nullptr;
    cudaGetSymbolAddress(&mb, g_minbits);
    cudaMemsetAsync(mb, 0x7F, (size_t)HH * NPTS * sizeof(unsigned int));

    sort_kernel<<<BB, 512>>>(planes, pts);
    seed_kernel<<<NPTS / 128, 128>>>(planes);

    dim3 grid(NTILE / WPB, NSQ, BB);   // (16, 8, 8) = 1024 blocks
    chamfer_kernel<<<grid, TP>>>();

    combine_kernel<<<NBLK, 256>>>();
    finalize_kernel<<<1, 128>>>(planes, (float*)d_out);
}

// round 9
// speedup vs baseline: 3.2274x; 3.2274x over previous
#include <cuda_runtime.h>
#include <math_constants.h>

// Problem shape (fixed by the dataset)
#define BB 8
#define HH 3
#define PP 4096
#define NS 16                   // q-splits per batch
#define TPQ (PP / NS)           // 256 q points per split
#define NPAIR (TPQ / 2)         // 128 packed q-pairs per split
#define TP 128                  // threads per chamfer block
#define PPT 4                   // p-points per thread
#define PBLK (TP * PPT)         // 512 p per block
#define NBLK 128
#define NPTS (BB * PP)

// per-(head,point) min as uint bits of nonneg float; reset to 0x7F7F7F7F
__device__ unsigned int g_minbits[HH * NPTS];
__device__ float g_partial[NBLK];

// ---- f32x2 helpers (Blackwell packed fp32: add/sub/mul/fma only) ----------
__device__ __forceinline__ unsigned long long pack2(float lo, float hi) {
    unsigned long long d;
    asm("mov.b64 %0, {%1, %2};" : "=l"(d) : "f"(lo), "f"(hi));
    return d;
}
__device__ __forceinline__ unsigned long long fma2(unsigned long long a,
                                                   unsigned long long b,
                                                   unsigned long long c) {
    unsigned long long d;
    asm("fma.rn.f32x2 %0, %1, %2, %3;" : "=l"(d) : "l"(a), "l"(b), "l"(c));
    return d;
}
// scalar min of packed result into two scalar accumulators
__device__ __forceinline__ void min2(float& a, float& b, unsigned long long t) {
    float lo, hi;
    asm("mov.b64 {%0, %1}, %2;" : "=f"(lo), "=f"(hi) : "l"(t));
    a = fminf(a, lo);
    b = fminf(b, hi);
}

// normalized plane normals + offset for batch b (fp32, Newton-refined rsqrt)
__device__ __forceinline__ void load_normals(const float* __restrict__ planes,
                                             int b, float nx[HH], float ny[HH],
                                             float nz[HH], float nc[HH]) {
#pragma unroll
    for (int h = 0; h < HH; h++) {
        const float* pl = planes + (b * HH + h) * 4;
        float x = pl[0], y = pl[1], z = pl[2];
        float nn  = x * x + y * y + z * z;
        float inv = rsqrtf(nn);
        inv = inv * (1.5f - 0.5f * nn * inv * inv);
        nx[h] = x * inv; ny[h] = y * inv; nz[h] = z * inv; nc[h] = pl[3];
    }
}

// ---------------------------------------------------------------------------
// Main kernel (R5 structure): block = (p-tile of 512, q-split of 256, batch).
// Inner loop per q-pair: 4 LDS.128 + 24 FFMA2 + 24 FMNMX covering 4p x 2q x 3h.
// Epilogue: val = max(min + |x_p|^2, 0), bitwise atomicMin (exact,
// order-independent -> deterministic).
// ---------------------------------------------------------------------------
__global__ __launch_bounds__(TP)
void chamfer_kernel(const float* __restrict__ planes,
                    const float* __restrict__ pts) {
    // per pair j: sA={(x0,x1),(y0,y1)}  sB={(z0,z1),(w0,w1)}
    //             sC={(d00,d01),(d10,d11)}  sD={(d20,d21)}
    __shared__ ulonglong2         sA[NPAIR];
    __shared__ ulonglong2         sB[NPAIR];
    __shared__ ulonglong2         sC[NPAIR];
    __shared__ unsigned long long sD[NPAIR];

    const int t    = threadIdx.x;
    const int tile = blockIdx.x;        // 0 .. PP/PBLK-1
    const int spl  = blockIdx.y;        // 0 .. NS-1
    const int b    = blockIdx.z;        // 0 .. BB-1

    float nx[HH], ny[HH], nz[HH], nc[HH];
    load_normals(planes, b, nx, ny, nz, nc);

    // ---- stage q-tile (NPAIR = TP: one pair per thread) ----
    const int qstart = b * PP + spl * TPQ;
#pragma unroll
    for (int j = t; j < NPAIR; j += TP) {
        const float* q = pts + (qstart + 2 * j) * 3;
        float x0 = q[0], y0 = q[1], z0 = q[2];
        float x1 = q[3], y1 = q[4], z1 = q[5];
        float w0 = x0 * x0 + y0 * y0 + z0 * z0;
        float w1 = x1 * x1 + y1 * y1 + z1 * z1;
        float d0[HH], d1[HH];
#pragma unroll
        for (int h = 0; h < HH; h++) {
            d0[h] = nx[h] * x0 + ny[h] * y0 + nz[h] * z0 + nc[h];
            d1[h] = nx[h] * x1 + ny[h] * y1 + nz[h] * z1 + nc[h];
        }
        ulonglong2 A, B, C;
        A.x = pack2(x0, x1);       A.y = pack2(y0, y1);
        B.x = pack2(z0, z1);       B.y = pack2(w0, w1);
        C.x = pack2(d0[0], d1[0]); C.y = pack2(d0[1], d1[1]);
        sA[j] = A; sB[j] = B; sC[j] = C;
        sD[j] = pack2(d0[2], d1[2]);
    }

    // ---- per-thread p constants: PPT p-points, stride TP apart ----
    unsigned long long MX[PPT], MY[PPT], MZ[PPT];
    unsigned long long Q0[PPT], Q1[PPT], Q2[PPT];
    float x2p[PPT];
    float m0a[PPT], m0b[PPT], m1a[PPT], m1b[PPT], m2a[PPT], m2b[PPT];
#pragma unroll
    for (int k = 0; k < PPT; k++) {
        const int p = tile * PBLK + k * TP + t;
        const float* P = pts + (b * PP + p) * 3;
        float ax = P[0], ay = P[1], az = P[2];
        float e0 = nx[0] * ax + ny[0] * ay + nz[0] * az + nc[0];
        float e1 = nx[1] * ax + ny[1] * ay + nz[1] * az + nc[1];
        float e2 = nx[2] * ax + ny[2] * ay + nz[2] * az + nc[2];
        MX[k] = pack2(-2.f * ax, -2.f * ax);
        MY[k] = pack2(-2.f * ay, -2.f * ay);
        MZ[k] = pack2(-2.f * az, -2.f * az);
        Q0[k] = pack2(4.f * e0, 4.f * e0);
        Q1[k] = pack2(4.f * e1, 4.f * e1);
        Q2[k] = pack2(4.f * e2, 4.f * e2);
        x2p[k] = ax * ax + ay * ay + az * az;
        m0a[k] = m0b[k] = CUDART_INF_F;
        m1a[k] = m1b[k] = CUDART_INF_F;
        m2a[k] = m2b[k] = CUDART_INF_F;
    }

    __syncthreads();

#pragma unroll 8
    for (int j = 0; j < NPAIR; j++) {
        ulonglong2 A = sA[j];
        ulonglong2 B = sB[j];
        ulonglong2 C = sC[j];
        unsigned long long D2 = sD[j];

#pragma unroll
        for (int k = 0; k < PPT; k++) {
            // acc = w_q - 2 x_p . x_q   (|x_p|^2 added in epilogue)
            unsigned long long acc = fma2(MX[k], A.x, B.y);
            acc = fma2(MY[k], A.y, acc);
            acc = fma2(MZ[k], B.x, acc);
            min2(m0a[k], m0b[k], fma2(Q0[k], C.x, acc));
            min2(m1a[k], m1b[k], fma2(Q1[k], C.y, acc));
            min2(m2a[k], m2b[k], fma2(Q2[k], D2,  acc));
        }
    }

    // epilogue: fold halves, add |x_p|^2, clamp, bitwise atomicMin
#pragma unroll
    for (int k = 0; k < PPT; k++) {
        const int i = b * PP + tile * PBLK + k * TP + t;
        float v0 = fmaxf(fminf(m0a[k], m0b[k]) + x2p[k], 0.0f);
        float v1 = fmaxf(fminf(m1a[k], m1b[k]) + x2p[k], 0.0f);
        float v2 = fmaxf(fminf(m2a[k], m2b[k]) + x2p[k], 0.0f);
        atomicMin(&g_minbits[0 * NPTS + i], __float_as_uint(v0));
        atomicMin(&g_minbits[1 * NPTS + i], __float_as_uint(v1));
        atomicMin(&g_minbits[2 * NPTS + i], __float_as_uint(v2));
    }
}

// ---------------------------------------------------------------------------
// Combine: sum the 3 head-mins per point, deterministic block tree-reduce.
// ---------------------------------------------------------------------------
__global__ __launch_bounds__(256)
void combine_kernel() {
    __shared__ float red[256];
    const int i = blockIdx.x * 256 + threadIdx.x;   // 0 .. NPTS-1

    float s = __uint_as_float(g_minbits[0 * NPTS + i])
            + __uint_as_float(g_minbits[1 * NPTS + i])
            + __uint_as_float(g_minbits[2 * NPTS + i]);

    red[threadIdx.x] = s;
    __syncthreads();
#pragma unroll
    for (int off = 128; off > 0; off >>= 1) {
        if (threadIdx.x < off) red[threadIdx.x] += red[threadIdx.x + off];
        __syncthreads();
    }
    if (threadIdx.x == 0) g_partial[blockIdx.x] = red[0];
}

// ---------------------------------------------------------------------------
// Finalize: parallel fp32 tree-reduce of partials + per-batch reg loss.
// ---------------------------------------------------------------------------
__global__ __launch_bounds__(128)
void finalize_kernel(const float* __restrict__ planes,
                     float* __restrict__ out) {
    __shared__ float red[128];
    __shared__ float regs[BB];
    const int t = threadIdx.x;

    red[t] = g_partial[t];
    __syncthreads();
#pragma unroll
    for (int off = 64; off > 0; off >>= 1) {
        if (t < off) red[t] += red[t + off];
        __syncthreads();
    }

    if (t < BB) {
        float nx[HH], ny[HH], nz[HH], nc[HH];
        load_normals(planes, t, nx, ny, nz, nc);
        float acc = 0.0f;
#pragma unroll
        for (int i = 0; i < HH; i++)
#pragma unroll
            for (int j = 0; j < HH; j++) {
                float g = nx[i] * nx[j] + ny[i] * ny[j] + nz[i] * nz[j]
                        - (i == j ? 1.0f : 0.0f);
                acc += g * g;
            }
        regs[t] = sqrtf(acc);
    }
    __syncthreads();

    if (t == 0) {
        float reg = 0.0f;
#pragma unroll
        for (int b = 0; b < BB; b++) reg += regs[b];
        // cham_x == cham_y by reflection symmetry -> factor 2
        float refl = 2.0f * red[0] / (float)(BB * PP);
        out[0] = refl + 25.0f * reg;
    }
}

// ---------------------------------------------------------------------------
extern "C" void kernel_launch(void* const* d_in, const int* in_sizes, int n_in,
                              void* d_out, int out_size) {
    const float* planes = (const float*)d_in[0];   // (8, 3, 4)
    const float* pts    = (const float*)d_in[1];   // (8, 4096, 3)
    // d_in[2], d_in[3] (voxel/cp grids) are unused by the reference.

    void* mb = nullptr;
    cudaGetSymbolAddress(&mb, g_minbits);
    cudaMemsetAsync(mb, 0x7F, (size_t)HH * NPTS * sizeof(unsigned int));

    dim3 grid(PP / PBLK, NS, BB);   // (8, 16, 8) = 1024 blocks
    chamfer_kernel<<<grid, TP>>>(planes, pts);

    combine_kernel<<<NBLK, 256>>>();
    finalize_kernel<<<1, 128>>>(planes, (float*)d_out);
}